// round 3
// baseline (speedup 1.0000x reference)
#include <cuda_runtime.h>
#include <cstddef>

#define NODES 64
#define DIM   256
#define TPB   256

// ---------- packed f32x2 helpers (Blackwell FFMA2 path) ----------
__device__ __forceinline__ unsigned long long fma2(unsigned long long a,
                                                   unsigned long long b,
                                                   unsigned long long c) {
    unsigned long long d;
    asm("fma.rn.f32x2 %0, %1, %2, %3;" : "=l"(d) : "l"(a), "l"(b), "l"(c));
    return d;
}
__device__ __forceinline__ unsigned long long bcast2(float v) {
    unsigned long long d;
    asm("mov.b64 %0, {%1, %1};" : "=l"(d) : "f"(v));
    return d;
}
__device__ __forceinline__ float2 unpack2(unsigned long long v) {
    float lo, hi;
    asm("mov.b64 {%0, %1}, %2;" : "=f"(lo), "=f"(hi) : "l"(v));
    return make_float2(lo, hi);
}

__device__ __forceinline__ float fast_tanh(float v) {
    // tanh(v) = 1 - 2/(exp(2v)+1); exact at saturation (exp->inf or 0)
    float e = __expf(2.0f * v);
    return 1.0f - __fdividef(2.0f, e + 1.0f);
}

__global__ __launch_bounds__(TPB, 4)
void adj_attn_kernel(const float* __restrict__ x,
                     const float* __restrict__ W1,
                     const float* __restrict__ W2,
                     const float* __restrict__ W3,
                     const float* __restrict__ bs,
                     const float* __restrict__ Vs,
                     float* __restrict__ out) {
    // t rows padded to 68 floats (272 B, 16B-aligned rows); chunk-swizzled.
    __shared__ __align__(16) float tS[NODES * 68];
    // Vs padded to 65 floats/row -> bank = (i + j) % 32, conflict-free bcast loads
    __shared__ float VsS[NODES * 65];
    __shared__ float lhsS[NODES];
    __shared__ float rhsS[NODES];
    __shared__ float redA[8];
    __shared__ float redB[8];

    const int b    = blockIdx.x;
    const int tid  = threadIdx.x;
    const int lane = tid & 31;
    const int w    = tid >> 5;

    const float* xb = x + (size_t)b * (NODES * DIM);
    const float  w1 = *W1;

    // ---- per-lane weight fragments: d = 4*lane and 128 + 4*lane ----
    const float4 w2a = *(const float4*)(W2 + 4 * lane);
    const float4 w2b = *(const float4*)(W2 + 128 + 4 * lane);
    const float4 w3a = *(const float4*)(W3 + 4 * lane);
    const float4 w3b = *(const float4*)(W3 + 128 + 4 * lane);

    // ---- stage Vs into padded smem (coalesced read, conflict-free write) ----
    #pragma unroll
    for (int q = 0; q < 16; q++) {
        int e = tid + q * TPB;
        int i = e >> 6, j = e & 63;
        VsS[i * 65 + j] = Vs[e];
    }

    // ---- lhs/rhs dot products: warp w handles rows 8w..8w+7 ----
    float a2[8], a3[8];
    #pragma unroll
    for (int r = 0; r < 8; r++) {
        const float* xr = xb + ((w << 3) + r) * DIM;
        float4 u = *(const float4*)(xr + (lane << 2));
        float4 v = *(const float4*)(xr + 128 + (lane << 2));
        a2[r] = u.x * w2a.x + u.y * w2a.y + u.z * w2a.z + u.w * w2a.w
              + v.x * w2b.x + v.y * w2b.y + v.z * w2b.z + v.w * w2b.w;
        a3[r] = u.x * w3a.x + u.y * w3a.y + u.z * w3a.z + u.w * w3a.w
              + v.x * w3b.x + v.y * w3b.y + v.z * w3b.z + v.w * w3b.w;
    }
    #pragma unroll
    for (int r = 0; r < 8; r++) {
        float s2 = a2[r], s3 = a3[r];
        #pragma unroll
        for (int sft = 16; sft > 0; sft >>= 1) {
            s2 += __shfl_xor_sync(0xffffffffu, s2, sft);
            s3 += __shfl_xor_sync(0xffffffffu, s3, sft);
        }
        if (lane == 0) {
            lhsS[(w << 3) + r] = w1 * s2;
            rhsS[(w << 3) + r] = s3;
        }
    }
    __syncthreads();

    // ---- t[j][k] = tanh(lhs[j]*rhs[k] + bs[j][k]), chunk-swizzled store ----
    {
        const int j  = tid >> 2;
        const int tq = tid & 3;
        const float  lj   = lhsS[j];
        const float* bsr  = bs + (j << 6);
        float*       trow = tS + j * 68;
        #pragma unroll
        for (int c = 0; c < 4; c++) {
            int k = (tq << 4) + (c << 2);
            float4 bv = *(const float4*)(bsr + k);
            float4 tv;
            tv.x = fast_tanh(fmaf(lj, rhsS[k + 0], bv.x));
            tv.y = fast_tanh(fmaf(lj, rhsS[k + 1], bv.y));
            tv.z = fast_tanh(fmaf(lj, rhsS[k + 2], bv.z));
            tv.w = fast_tanh(fmaf(lj, rhsS[k + 3], bv.w));
            int ch  = k >> 2;
            int pch = ch ^ ((ch >> 3) & 1);   // 16B-chunk swizzle
            *(float4*)(trow + (pch << 2)) = tv;
        }
    }
    __syncthreads();

    // ---- s = Vs @ t with packed f32x2 FMA: thread tile 2 rows x 8 cols ----
    const int kg = tid & 7;        // k-group: k0 = 8*kg
    const int ig = tid >> 3;       // i-group: i0 = 2*ig
    const int i0 = ig << 1;
    const int k0 = kg << 3;
    const int c0 = 2 * kg;
    const int c1 = 2 * kg + 1;
    const int off0 = (c0 ^ ((c0 >> 3) & 1)) << 2;  // float offset of swizzled chunk
    const int off1 = (c1 ^ ((c1 >> 3) & 1)) << 2;

    const float* vr0 = VsS + i0 * 65;
    const float* vr1 = vr0 + 65;

    unsigned long long acc[8];
    #pragma unroll
    for (int i = 0; i < 8; i++) acc[i] = 0ull;

    #pragma unroll 4
    for (int j = 0; j < NODES; j++) {
        const float* tr = tS + j * 68;
        ulonglong2 ta = *(const ulonglong2*)(tr + off0);  // k0..k0+3
        ulonglong2 tb = *(const ulonglong2*)(tr + off1);  // k0+4..k0+7
        unsigned long long v0 = bcast2(vr0[j]);
        unsigned long long v1 = bcast2(vr1[j]);
        acc[0] = fma2(v0, ta.x, acc[0]);
        acc[1] = fma2(v0, ta.y, acc[1]);
        acc[2] = fma2(v0, tb.x, acc[2]);
        acc[3] = fma2(v0, tb.y, acc[3]);
        acc[4] = fma2(v1, ta.x, acc[4]);
        acc[5] = fma2(v1, ta.y, acc[5]);
        acc[6] = fma2(v1, tb.x, acc[6]);
        acc[7] = fma2(v1, tb.y, acc[7]);
    }

    // unpack: ev[0..7] = row i0 (k0..k0+7), ev[8..15] = row i0+1
    float ev[16];
    #pragma unroll
    for (int i = 0; i < 8; i++) {
        float2 p = unpack2(acc[i]);
        ev[2 * i]     = p.x;
        ev[2 * i + 1] = p.y;
    }

    // ---- softmax over the 4096 scores of this batch element ----
    float m = ev[0];
    #pragma unroll
    for (int i = 1; i < 16; i++) m = fmaxf(m, ev[i]);
    #pragma unroll
    for (int sft = 16; sft > 0; sft >>= 1)
        m = fmaxf(m, __shfl_xor_sync(0xffffffffu, m, sft));
    if (lane == 0) redA[w] = m;
    __syncthreads();
    float bm = redA[0];
    #pragma unroll
    for (int i = 1; i < 8; i++) bm = fmaxf(bm, redA[i]);

    float lsum = 0.0f;
    #pragma unroll
    for (int i = 0; i < 16; i++) {
        ev[i] = __expf(ev[i] - bm);
        lsum += ev[i];
    }
    #pragma unroll
    for (int sft = 16; sft > 0; sft >>= 1)
        lsum += __shfl_xor_sync(0xffffffffu, lsum, sft);
    if (lane == 0) redB[w] = lsum;
    __syncthreads();
    float tot = redB[0];
    #pragma unroll
    for (int i = 1; i < 8; i++) tot += redB[i];
    const float inv = 1.0f / tot;

    // ---- write out (each thread: 2 rows x 8 contiguous cols) ----
    float* orow = out + (size_t)b * (NODES * NODES) + i0 * NODES + k0;
    float4 o;
    o.x = ev[0] * inv;  o.y = ev[1] * inv;  o.z = ev[2] * inv;  o.w = ev[3] * inv;
    *(float4*)(orow + 0) = o;
    o.x = ev[4] * inv;  o.y = ev[5] * inv;  o.z = ev[6] * inv;  o.w = ev[7] * inv;
    *(float4*)(orow + 4) = o;
    o.x = ev[8] * inv;  o.y = ev[9] * inv;  o.z = ev[10] * inv; o.w = ev[11] * inv;
    *(float4*)(orow + NODES + 0) = o;
    o.x = ev[12] * inv; o.y = ev[13] * inv; o.z = ev[14] * inv; o.w = ev[15] * inv;
    *(float4*)(orow + NODES + 4) = o;
}

extern "C" void kernel_launch(void* const* d_in, const int* in_sizes, int n_in,
                              void* d_out, int out_size) {
    const float* x  = (const float*)d_in[0];
    const float* W1 = (const float*)d_in[1];
    const float* W2 = (const float*)d_in[2];
    const float* W3 = (const float*)d_in[3];
    const float* bs = (const float*)d_in[4];
    const float* Vs = (const float*)d_in[5];
    float* out = (float*)d_out;

    const int B = in_sizes[0] / (NODES * DIM);  // 4096
    adj_attn_kernel<<<B, TPB>>>(x, W1, W2, W3, bs, Vs, out);
}

// round 4
// speedup vs baseline: 1.2668x; 1.2668x over previous
#include <cuda_runtime.h>
#include <cstddef>

#define NODES 64
#define DIM   256
#define TPB   256
#define TSTR  68   // padded row stride (floats) for tS and VsT: 272B, 16B-aligned

// ---------- packed f32x2 helpers (Blackwell FFMA2 path) ----------
__device__ __forceinline__ unsigned long long fma2(unsigned long long a,
                                                   unsigned long long b,
                                                   unsigned long long c) {
    unsigned long long d;
    asm("fma.rn.f32x2 %0, %1, %2, %3;" : "=l"(d) : "l"(a), "l"(b), "l"(c));
    return d;
}
__device__ __forceinline__ unsigned long long bcast2(float v) {
    unsigned long long d;
    asm("mov.b64 %0, {%1, %1};" : "=l"(d) : "f"(v));
    return d;
}
__device__ __forceinline__ float2 unpack2(unsigned long long v) {
    float lo, hi;
    asm("mov.b64 {%0, %1}, %2;" : "=f"(lo), "=f"(hi) : "l"(v));
    return make_float2(lo, hi);
}

__device__ __forceinline__ float fast_tanh(float v) {
    // tanh(v) = 1 - 2/(exp(2v)+1); exact at saturation
    float e = __expf(2.0f * v);
    return 1.0f - __fdividef(2.0f, e + 1.0f);
}

__global__ __launch_bounds__(TPB, 4)
void adj_attn_kernel(const float* __restrict__ x,
                     const float* __restrict__ W1,
                     const float* __restrict__ W2,
                     const float* __restrict__ W3,
                     const float* __restrict__ bs,
                     const float* __restrict__ Vs,
                     float* __restrict__ out) {
    __shared__ __align__(16) float tS[NODES * TSTR];    // t rows, plain layout
    __shared__ __align__(16) float VsT[NODES * TSTR];   // Vs TRANSPOSED: VsT[j][i]
    __shared__ float lhsS[NODES];
    __shared__ float rhsS[NODES];
    __shared__ float redA[8];
    __shared__ float redB[8];

    const int b    = blockIdx.x;
    const int tid  = threadIdx.x;
    const int lane = tid & 31;
    const int w    = tid >> 5;

    const float* xb = x + (size_t)b * (NODES * DIM);
    const float  w1 = *W1;

    // ---- per-lane weight fragments: d = 4*lane and 128 + 4*lane ----
    const float4 w2a = *(const float4*)(W2 + 4 * lane);
    const float4 w2b = *(const float4*)(W2 + 128 + 4 * lane);
    const float4 w3a = *(const float4*)(W3 + 4 * lane);
    const float4 w3b = *(const float4*)(W3 + 128 + 4 * lane);

    // ---- stage Vs TRANSPOSED into smem (coalesced read) ----
    #pragma unroll
    for (int q = 0; q < 16; q++) {
        int e = tid + q * TPB;
        int i = e >> 6, j = e & 63;
        VsT[j * TSTR + i] = Vs[e];     // one-time staging; conflicts acceptable
    }

    // ---- lhs/rhs dot products: warp w handles rows 8w..8w+7 ----
    float a2[8], a3[8];
    #pragma unroll
    for (int r = 0; r < 8; r++) {
        const float* xr = xb + ((w << 3) + r) * DIM;
        float4 u = *(const float4*)(xr + (lane << 2));
        float4 v = *(const float4*)(xr + 128 + (lane << 2));
        a2[r] = u.x * w2a.x + u.y * w2a.y + u.z * w2a.z + u.w * w2a.w
              + v.x * w2b.x + v.y * w2b.y + v.z * w2b.z + v.w * w2b.w;
        a3[r] = u.x * w3a.x + u.y * w3a.y + u.z * w3a.z + u.w * w3a.w
              + v.x * w3b.x + v.y * w3b.y + v.z * w3b.z + v.w * w3b.w;
    }
    #pragma unroll
    for (int r = 0; r < 8; r++) {
        float s2 = a2[r], s3 = a3[r];
        #pragma unroll
        for (int sft = 16; sft > 0; sft >>= 1) {
            s2 += __shfl_xor_sync(0xffffffffu, s2, sft);
            s3 += __shfl_xor_sync(0xffffffffu, s3, sft);
        }
        if (lane == 0) {
            lhsS[(w << 3) + r] = w1 * s2;
            rhsS[(w << 3) + r] = s3;
        }
    }
    __syncthreads();

    // ---- t[j][k] = tanh(lhs[j]*rhs[k] + bs[j][k]), plain row layout ----
    {
        const int j  = tid >> 2;
        const int tq = tid & 3;
        const float  lj   = lhsS[j];
        const float* bsr  = bs + (j << 6);
        float*       trow = tS + j * TSTR;
        #pragma unroll
        for (int c = 0; c < 4; c++) {
            int k = (tq << 4) + (c << 2);
            float4 bv = *(const float4*)(bsr + k);
            float4 rv = *(const float4*)(rhsS + k);
            float4 tv;
            tv.x = fast_tanh(fmaf(lj, rv.x, bv.x));
            tv.y = fast_tanh(fmaf(lj, rv.y, bv.y));
            tv.z = fast_tanh(fmaf(lj, rv.z, bv.z));
            tv.w = fast_tanh(fmaf(lj, rv.w, bv.w));
            *(float4*)(trow + k) = tv;
        }
    }
    __syncthreads();

    // ---- s = Vs @ t : warp owns rows i0..i0+7, lane owns cols 2*lane..+1 ----
    // VsT row gives packed (i,i+1) f32x2 pairs via broadcast LDS.128 (1 wf each);
    // t contributes 8B/lane via LDS.64 (2 wf/warp). fma2 does 2 rows at once.
    const int i0 = w << 3;
    const int k0 = lane << 1;

    unsigned long long acc[8];   // acc[2p+kk] = rows (i0+2p, i0+2p+1), col k0+kk
    #pragma unroll
    for (int i = 0; i < 8; i++) acc[i] = 0ull;

    #pragma unroll 8
    for (int j = 0; j < NODES; j++) {
        const float* vr = VsT + j * TSTR + i0;
        ulonglong2 va = *(const ulonglong2*)(vr);      // pairs (i0,i0+1),(i0+2,i0+3)
        ulonglong2 vb = *(const ulonglong2*)(vr + 4);  // pairs (i0+4,..),(i0+6,..)
        float2 tv = *(const float2*)(tS + j * TSTR + k0);
        unsigned long long b0 = bcast2(tv.x);
        unsigned long long b1 = bcast2(tv.y);
        acc[0] = fma2(va.x, b0, acc[0]);
        acc[1] = fma2(va.x, b1, acc[1]);
        acc[2] = fma2(va.y, b0, acc[2]);
        acc[3] = fma2(va.y, b1, acc[3]);
        acc[4] = fma2(vb.x, b0, acc[4]);
        acc[5] = fma2(vb.x, b1, acc[5]);
        acc[6] = fma2(vb.y, b0, acc[6]);
        acc[7] = fma2(vb.y, b1, acc[7]);
    }

    // unpack: ev[r][kk] = s[i0+r][k0+kk]
    float ev[8][2];
    #pragma unroll
    for (int p = 0; p < 4; p++) {
        #pragma unroll
        for (int kk = 0; kk < 2; kk++) {
            float2 u = unpack2(acc[2 * p + kk]);
            ev[2 * p][kk]     = u.x;
            ev[2 * p + 1][kk] = u.y;
        }
    }

    // ---- softmax over the 4096 scores of this batch element ----
    float m = ev[0][0];
    #pragma unroll
    for (int r = 0; r < 8; r++) {
        m = fmaxf(m, ev[r][0]);
        m = fmaxf(m, ev[r][1]);
    }
    #pragma unroll
    for (int sft = 16; sft > 0; sft >>= 1)
        m = fmaxf(m, __shfl_xor_sync(0xffffffffu, m, sft));
    if (lane == 0) redA[w] = m;
    __syncthreads();
    float bm = redA[0];
    #pragma unroll
    for (int i = 1; i < 8; i++) bm = fmaxf(bm, redA[i]);

    float lsum = 0.0f;
    #pragma unroll
    for (int r = 0; r < 8; r++) {
        ev[r][0] = __expf(ev[r][0] - bm);
        ev[r][1] = __expf(ev[r][1] - bm);
        lsum += ev[r][0] + ev[r][1];
    }
    #pragma unroll
    for (int sft = 16; sft > 0; sft >>= 1)
        lsum += __shfl_xor_sync(0xffffffffu, lsum, sft);
    if (lane == 0) redB[w] = lsum;
    __syncthreads();
    float tot = redB[0];
    #pragma unroll
    for (int i = 1; i < 8; i++) tot += redB[i];
    const float inv = 1.0f / tot;

    // ---- write out: warp writes rows i0..i0+7, lane cols k0..k0+1 (coalesced) ----
    float* ob = out + (size_t)b * (NODES * NODES) + (size_t)i0 * NODES + k0;
    #pragma unroll
    for (int r = 0; r < 8; r++) {
        float2 o;
        o.x = ev[r][0] * inv;
        o.y = ev[r][1] * inv;
        *(float2*)(ob + r * NODES) = o;
    }
}

extern "C" void kernel_launch(void* const* d_in, const int* in_sizes, int n_in,
                              void* d_out, int out_size) {
    const float* x  = (const float*)d_in[0];
    const float* W1 = (const float*)d_in[1];
    const float* W2 = (const float*)d_in[2];
    const float* W3 = (const float*)d_in[3];
    const float* bs = (const float*)d_in[4];
    const float* Vs = (const float*)d_in[5];
    float* out = (float*)d_out;

    const int B = in_sizes[0] / (NODES * DIM);  // 4096
    adj_attn_kernel<<<B, TPB>>>(x, W1, W2, W3, bs, Vs, out);
}

// round 6
// speedup vs baseline: 1.4808x; 1.1689x over previous
#include <cuda_runtime.h>
#include <cuda_bf16.h>
#include <cstdint>
#include <cstddef>

#define NODES 64
#define DIM   256
#define TPB   256
#define PSTR  72    // padded row stride in bf16 elements (144 B, 16B-aligned, conflict-free ldsm)

// ---------------- device scratch (grid-constant precompute) ----------------
__device__ __align__(16) __nv_bfloat16 g_VsHi[64 * PSTR];
__device__ __align__(16) __nv_bfloat16 g_VsLo[64 * PSTR];
__device__ __align__(16) float         g_bsT[4096];     // bsT[n][j] = bs[j][n]

// ---------------- helpers ----------------
__device__ __forceinline__ uint32_t smem_u32(const void* p) {
    uint32_t a;
    asm("{ .reg .u64 t; cvta.to.shared.u64 t, %1; cvt.u32.u64 %0, t; }" : "=r"(a) : "l"(p));
    return a;
}

__device__ __forceinline__ void ldsm_x4(uint32_t& r0, uint32_t& r1,
                                        uint32_t& r2, uint32_t& r3, uint32_t addr) {
    asm volatile("ldmatrix.sync.aligned.m8n8.x4.shared.b16 {%0,%1,%2,%3}, [%4];"
                 : "=r"(r0), "=r"(r1), "=r"(r2), "=r"(r3) : "r"(addr));
}

__device__ __forceinline__ void mma_bf16(float& c0, float& c1, float& c2, float& c3,
                                         uint32_t a0, uint32_t a1, uint32_t a2, uint32_t a3,
                                         uint32_t b0, uint32_t b1) {
    asm volatile(
        "mma.sync.aligned.m16n8k16.row.col.f32.bf16.bf16.f32 "
        "{%0,%1,%2,%3}, {%4,%5,%6,%7}, {%8,%9}, {%0,%1,%2,%3};"
        : "+f"(c0), "+f"(c1), "+f"(c2), "+f"(c3)
        : "r"(a0), "r"(a1), "r"(a2), "r"(a3), "r"(b0), "r"(b1));
}

__device__ __forceinline__ float fast_tanh(float v) {
    float e = __expf(2.0f * v);
    return 1.0f - __fdividef(2.0f, e + 1.0f);
}

__device__ __forceinline__ uint32_t pack_hi(float v0, float v1,
                                            float& r0, float& r1) {
    __nv_bfloat16 h0 = __float2bfloat16(v0);
    __nv_bfloat16 h1 = __float2bfloat16(v1);
    r0 = v0 - __bfloat162float(h0);
    r1 = v1 - __bfloat162float(h1);
    return (uint32_t)__bfloat16_as_ushort(h0)
         | ((uint32_t)__bfloat16_as_ushort(h1) << 16);
}
__device__ __forceinline__ uint32_t pack_lo(float r0, float r1) {
    return (uint32_t)__bfloat16_as_ushort(__float2bfloat16(r0))
         | ((uint32_t)__bfloat16_as_ushort(__float2bfloat16(r1)) << 16);
}

// ---------------- precompute: Vs -> bf16 hi/lo (padded rows), bsT ----------------
__global__ void precompute_kernel(const float* __restrict__ bs,
                                  const float* __restrict__ Vs) {
    int e = blockIdx.x * blockDim.x + threadIdx.x;   // 0..4095
    int i = e >> 6, j = e & 63;
    float v = Vs[e];
    __nv_bfloat16 hi = __float2bfloat16(v);
    float rem = v - __bfloat162float(hi);
    g_VsHi[i * PSTR + j] = hi;
    g_VsLo[i * PSTR + j] = __float2bfloat16(rem);
    g_bsT[i * 64 + j] = bs[j * 64 + i];              // (n=i, j)
}

// ---------------- main kernel: 1 batch element per block ----------------
__global__ __launch_bounds__(TPB)
void adj_attn_mma(const float* __restrict__ x,
                  const float* __restrict__ W1,
                  const float* __restrict__ W2,
                  const float* __restrict__ W3,
                  float* __restrict__ out) {
    __shared__ __align__(16) __nv_bfloat16 VsHiS[64 * PSTR];
    __shared__ __align__(16) __nv_bfloat16 VsLoS[64 * PSTR];
    __shared__ __align__(16) __nv_bfloat16 tHiS[64 * PSTR];   // tT[n][j] hi
    __shared__ __align__(16) __nv_bfloat16 tLoS[64 * PSTR];   // tT[n][j] lo
    __shared__ float lhsS[NODES];
    __shared__ float rhsS[NODES];
    __shared__ float redS[16];

    const int tid  = threadIdx.x;
    const int lane = tid & 31;
    const int w    = tid >> 5;

    // ---- stage Vs hi/lo from precomputed global (coalesced uint4) ----
    {
        const uint4* shi = (const uint4*)g_VsHi;
        const uint4* slo = (const uint4*)g_VsLo;
        uint4* dhi = (uint4*)VsHiS;
        uint4* dlo = (uint4*)VsLoS;
        for (int e = tid; e < (64 * PSTR * 2) / 16; e += TPB) {
            dhi[e] = shi[e];
            dlo[e] = slo[e];
        }
    }

    // ---- lhs/rhs dot products: warp w handles rows 8w..8w+7 ----
    const float w1   = *W1;
    const float4 w2a = *(const float4*)(W2 + 4 * lane);
    const float4 w2b = *(const float4*)(W2 + 128 + 4 * lane);
    const float4 w3a = *(const float4*)(W3 + 4 * lane);
    const float4 w3b = *(const float4*)(W3 + 128 + 4 * lane);
    const float* xb  = x + (size_t)blockIdx.x * (NODES * DIM);

    float a2[8], a3[8];
    #pragma unroll
    for (int r = 0; r < 8; r++) {
        const float* xr = xb + ((w << 3) + r) * DIM;
        float4 u = *(const float4*)(xr + (lane << 2));
        float4 v = *(const float4*)(xr + 128 + (lane << 2));
        a2[r] = u.x * w2a.x + u.y * w2a.y + u.z * w2a.z + u.w * w2a.w
              + v.x * w2b.x + v.y * w2b.y + v.z * w2b.z + v.w * w2b.w;
        a3[r] = u.x * w3a.x + u.y * w3a.y + u.z * w3a.z + u.w * w3a.w
              + v.x * w3b.x + v.y * w3b.y + v.z * w3b.z + v.w * w3b.w;
    }
    #pragma unroll
    for (int r = 0; r < 8; r++) {
        float s2 = a2[r], s3 = a3[r];
        #pragma unroll
        for (int sft = 16; sft > 0; sft >>= 1) {
            s2 += __shfl_xor_sync(0xffffffffu, s2, sft);
            s3 += __shfl_xor_sync(0xffffffffu, s3, sft);
        }
        if (lane == 0) {
            lhsS[(w << 3) + r] = w1 * s2;
            rhsS[(w << 3) + r] = s3;
        }
    }
    __syncthreads();

    // ---- build tT[n][j] = tanh(lhs[j]*rhs[n] + bsT[n][j]) as bf16 hi/lo ----
    {
        const int n  = tid >> 2;
        const int j0 = (tid & 3) * 16;
        const float rv = rhsS[n];
        #pragma unroll
        for (int c = 0; c < 2; c++) {
            const int j = j0 + c * 8;
            float4 l0 = *(const float4*)(lhsS + j);
            float4 l1 = *(const float4*)(lhsS + j + 4);
            float4 b0 = *(const float4*)(g_bsT + n * 64 + j);
            float4 b1 = *(const float4*)(g_bsT + n * 64 + j + 4);
            float tv[8];
            tv[0] = fast_tanh(fmaf(l0.x, rv, b0.x));
            tv[1] = fast_tanh(fmaf(l0.y, rv, b0.y));
            tv[2] = fast_tanh(fmaf(l0.z, rv, b0.z));
            tv[3] = fast_tanh(fmaf(l0.w, rv, b0.w));
            tv[4] = fast_tanh(fmaf(l1.x, rv, b1.x));
            tv[5] = fast_tanh(fmaf(l1.y, rv, b1.y));
            tv[6] = fast_tanh(fmaf(l1.z, rv, b1.z));
            tv[7] = fast_tanh(fmaf(l1.w, rv, b1.w));
            uint4 hw, lw;
            float r0, r1;
            hw.x = pack_hi(tv[0], tv[1], r0, r1); lw.x = pack_lo(r0, r1);
            hw.y = pack_hi(tv[2], tv[3], r0, r1); lw.y = pack_lo(r0, r1);
            hw.z = pack_hi(tv[4], tv[5], r0, r1); lw.z = pack_lo(r0, r1);
            hw.w = pack_hi(tv[6], tv[7], r0, r1); lw.w = pack_lo(r0, r1);
            *(uint4*)((char*)tHiS + (n * PSTR + j) * 2) = hw;
            *(uint4*)((char*)tLoS + (n * PSTR + j) * 2) = lw;
        }
    }
    __syncthreads();

    // ---- warp-level GEMM: warp w -> rows 16*(w>>1).., cols 32*(w&1).. ----
    const int mt = w >> 1;
    const int nh = w & 1;

    const uint32_t sVsHi = smem_u32(VsHiS);
    const uint32_t sVsLo = smem_u32(VsLoS);
    const uint32_t sTHi  = smem_u32(tHiS);
    const uint32_t sTLo  = smem_u32(tLoS);

    // per-lane ldmatrix base offsets (bytes)
    const uint32_t aOff = (uint32_t)(((16 * mt + (lane & 15)) * PSTR
                                      + ((lane >> 4) & 1) * 8) * 2);
    const uint32_t bOff0 = (uint32_t)(((nh * 32 + (lane & 7) + ((lane >> 4) & 1) * 8) * PSTR
                                       + ((lane >> 3) & 1) * 8) * 2);
    const uint32_t bOff1 = bOff0 + (uint32_t)(16 * PSTR * 2);

    float acc[16];
    #pragma unroll
    for (int i = 0; i < 16; i++) acc[i] = 0.0f;

    const uint32_t aB[3] = {sVsHi, sVsHi, sVsLo};
    const uint32_t bB[3] = {sTHi,  sTLo,  sTHi};

    #pragma unroll
    for (int p = 0; p < 3; p++) {
        #pragma unroll
        for (int ks = 0; ks < 4; ks++) {
            const uint32_t joff = (uint32_t)(ks * 32);   // 16 elems * 2B
            uint32_t a0, a1, a2r, a3r, b0, b1, b2, b3, b4, b5, b6, b7;
            ldsm_x4(a0, a1, a2r, a3r, aB[p] + aOff + joff);
            ldsm_x4(b0, b1, b2, b3,   bB[p] + bOff0 + joff);
            ldsm_x4(b4, b5, b6, b7,   bB[p] + bOff1 + joff);
            mma_bf16(acc[0],  acc[1],  acc[2],  acc[3],  a0, a1, a2r, a3r, b0, b1);
            mma_bf16(acc[4],  acc[5],  acc[6],  acc[7],  a0, a1, a2r, a3r, b2, b3);
            mma_bf16(acc[8],  acc[9],  acc[10], acc[11], a0, a1, a2r, a3r, b4, b5);
            mma_bf16(acc[12], acc[13], acc[14], acc[15], a0, a1, a2r, a3r, b6, b7);
        }
    }

    // ---- softmax over all 4096 scores of this batch element ----
    float m = acc[0];
    #pragma unroll
    for (int i = 1; i < 16; i++) m = fmaxf(m, acc[i]);
    #pragma unroll
    for (int sft = 16; sft > 0; sft >>= 1)
        m = fmaxf(m, __shfl_xor_sync(0xffffffffu, m, sft));
    if (lane == 0) redS[w] = m;
    __syncthreads();
    float bm = redS[0];
    #pragma unroll
    for (int i = 1; i < 8; i++) bm = fmaxf(bm, redS[i]);

    float lsum = 0.0f;
    #pragma unroll
    for (int i = 0; i < 16; i++) {
        acc[i] = __expf(acc[i] - bm);
        lsum += acc[i];
    }
    #pragma unroll
    for (int sft = 16; sft > 0; sft >>= 1)
        lsum += __shfl_xor_sync(0xffffffffu, lsum, sft);
    if (lane == 0) redS[8 + w] = lsum;
    __syncthreads();
    float tot = redS[8];
    #pragma unroll
    for (int i = 1; i < 8; i++) tot += redS[8 + i];
    const float inv = 1.0f / tot;

    // ---- store: mma C layout -> rows {16mt+lane/4, +8}, cols 32nh+g*8+(lane%4)*2 ----
    float* ob = out + (size_t)blockIdx.x * (NODES * NODES);
    const int row0 = 16 * mt + (lane >> 2);
    const int col0 = 32 * nh + (lane & 3) * 2;
    #pragma unroll
    for (int g = 0; g < 4; g++) {
        float2 o;
        o.x = acc[g * 4 + 0] * inv;
        o.y = acc[g * 4 + 1] * inv;
        *(float2*)(ob + row0 * NODES + col0 + g * 8) = o;
        o.x = acc[g * 4 + 2] * inv;
        o.y = acc[g * 4 + 3] * inv;
        *(float2*)(ob + (row0 + 8) * NODES + col0 + g * 8) = o;
    }
}

extern "C" void kernel_launch(void* const* d_in, const int* in_sizes, int n_in,
                              void* d_out, int out_size) {
    const float* x  = (const float*)d_in[0];
    const float* W1 = (const float*)d_in[1];
    const float* W2 = (const float*)d_in[2];
    const float* W3 = (const float*)d_in[3];
    const float* bs = (const float*)d_in[4];
    const float* Vs = (const float*)d_in[5];
    float* out = (float*)d_out;

    const int B = in_sizes[0] / (NODES * DIM);   // 4096
    precompute_kernel<<<16, 256>>>(bs, Vs);
    adj_attn_mma<<<B, TPB>>>(x, W1, W2, W3, out);
}

// round 7
// speedup vs baseline: 1.7877x; 1.2073x over previous
#include <cuda_runtime.h>
#include <cuda_bf16.h>
#include <cstdint>
#include <cstddef>

#define NODES 64
#define DIM   256
#define TPB   256
#define PSTR  72    // padded row stride in bf16 elems (144 B, conflict-free ldsm)

// ---------------- device scratch (grid-constant precompute) ----------------
// A (=Vs) mma fragments, per-lane layout: idx = mt*512 + ks*128 + lane*4 + q
__device__ __align__(16) uint32_t g_AfHi[2048];
__device__ __align__(16) uint32_t g_AfLo[2048];
__device__ __align__(16) float    g_bsT[4096];    // bsT[n][j] = bs[j][n]

// ---------------- helpers ----------------
__device__ __forceinline__ uint32_t smem_u32(const void* p) {
    uint32_t a;
    asm("{ .reg .u64 t; cvta.to.shared.u64 t, %1; cvt.u32.u64 %0, t; }" : "=r"(a) : "l"(p));
    return a;
}

__device__ __forceinline__ void ldsm_x4(uint32_t& r0, uint32_t& r1,
                                        uint32_t& r2, uint32_t& r3, uint32_t addr) {
    asm volatile("ldmatrix.sync.aligned.m8n8.x4.shared.b16 {%0,%1,%2,%3}, [%4];"
                 : "=r"(r0), "=r"(r1), "=r"(r2), "=r"(r3) : "r"(addr));
}

__device__ __forceinline__ void mma_bf16(float& c0, float& c1, float& c2, float& c3,
                                         uint32_t a0, uint32_t a1, uint32_t a2, uint32_t a3,
                                         uint32_t b0, uint32_t b1) {
    asm volatile(
        "mma.sync.aligned.m16n8k16.row.col.f32.bf16.bf16.f32 "
        "{%0,%1,%2,%3}, {%4,%5,%6,%7}, {%8,%9}, {%0,%1,%2,%3};"
        : "+f"(c0), "+f"(c1), "+f"(c2), "+f"(c3)
        : "r"(a0), "r"(a1), "r"(a2), "r"(a3), "r"(b0), "r"(b1));
}

__device__ __forceinline__ float fast_tanh(float v) {
    float e = __expf(2.0f * v);
    return 1.0f - __fdividef(2.0f, e + 1.0f);
}

__device__ __forceinline__ uint32_t pack_hi(float v0, float v1,
                                            float& r0, float& r1) {
    __nv_bfloat16 h0 = __float2bfloat16(v0);
    __nv_bfloat16 h1 = __float2bfloat16(v1);
    r0 = v0 - __bfloat162float(h0);
    r1 = v1 - __bfloat162float(h1);
    return (uint32_t)__bfloat16_as_ushort(h0)
         | ((uint32_t)__bfloat16_as_ushort(h1) << 16);
}
__device__ __forceinline__ uint32_t pack_lo(float r0, float r1) {
    return (uint32_t)__bfloat16_as_ushort(__float2bfloat16(r0))
         | ((uint32_t)__bfloat16_as_ushort(__float2bfloat16(r1)) << 16);
}

// merge-tree warp reduce of 8 per-lane partial sets -> per-lane row total.
// Row for lane l: R = 4*b2 + 2*b3 + b4   (b_i = bit i of lane)
__device__ __forceinline__ float reduce8(float v[8], int lane) {
    float m[4];
    #pragma unroll
    for (int p = 0; p < 4; p++) {
        float s = (lane & 16) ? v[2 * p]     : v[2 * p + 1];
        float k = (lane & 16) ? v[2 * p + 1] : v[2 * p];
        m[p] = k + __shfl_xor_sync(0xffffffffu, s, 16);
    }
    float n[2];
    #pragma unroll
    for (int p = 0; p < 2; p++) {
        float s = (lane & 8) ? m[2 * p]     : m[2 * p + 1];
        float k = (lane & 8) ? m[2 * p + 1] : m[2 * p];
        n[p] = k + __shfl_xor_sync(0xffffffffu, s, 8);
    }
    float s = (lane & 4) ? n[0] : n[1];
    float k = (lane & 4) ? n[1] : n[0];
    float o = k + __shfl_xor_sync(0xffffffffu, s, 4);
    o += __shfl_xor_sync(0xffffffffu, o, 2);
    o += __shfl_xor_sync(0xffffffffu, o, 1);
    return o;
}

// ---------------- precompute: A mma fragments (hi/lo) + bsT ----------------
__global__ void precompute_kernel(const float* __restrict__ bs,
                                  const float* __restrict__ Vs) {
    int e = blockIdx.x * blockDim.x + threadIdx.x;   // 0..4095
    if (e < 2048) {
        int mt = e >> 9, ks = (e >> 7) & 3, lane = (e >> 2) & 31, q = e & 3;
        int row = 16 * mt + (lane >> 2) + (q & 1) * 8;
        int col = 16 * ks + (lane & 3) * 2 + ((q >> 1) & 1) * 8;
        float v0 = Vs[row * 64 + col];
        float v1 = Vs[row * 64 + col + 1];
        float r0, r1;
        uint32_t hw = pack_hi(v0, v1, r0, r1);
        g_AfHi[e] = hw;
        g_AfLo[e] = pack_lo(r0, r1);
    }
    {
        int i = e >> 6, j = e & 63;
        g_bsT[e] = bs[j * 64 + i];
    }
}

// ---------------- main kernel: 1 batch element per block ----------------
__global__ __launch_bounds__(TPB, 4)
void adj_attn_mma(const float* __restrict__ x,
                  const float* __restrict__ W1,
                  const float* __restrict__ W2,
                  const float* __restrict__ W3,
                  float* __restrict__ out) {
    __shared__ __align__(16) __nv_bfloat16 tHiS[64 * PSTR];   // tT[n][j] hi
    __shared__ __align__(16) __nv_bfloat16 tLoS[64 * PSTR];   // tT[n][j] lo
    __shared__ float lhsS[NODES];
    __shared__ float rhsS[NODES];
    __shared__ float redS[16];

    const int tid  = threadIdx.x;
    const int lane = tid & 31;
    const int w    = tid >> 5;

    // ---- lhs/rhs dot products: warp w handles rows 8w..8w+7 ----
    const float w1   = *W1;
    const float4 w2a = *(const float4*)(W2 + 4 * lane);
    const float4 w2b = *(const float4*)(W2 + 128 + 4 * lane);
    const float4 w3a = *(const float4*)(W3 + 4 * lane);
    const float4 w3b = *(const float4*)(W3 + 128 + 4 * lane);
    const float* xb  = x + (size_t)blockIdx.x * (NODES * DIM);

    float a2[8], a3[8];
    #pragma unroll
    for (int r = 0; r < 8; r++) {
        const float* xr = xb + ((w << 3) + r) * DIM;
        float4 u = *(const float4*)(xr + (lane << 2));
        float4 v = *(const float4*)(xr + 128 + (lane << 2));
        a2[r] = u.x * w2a.x + u.y * w2a.y + u.z * w2a.z + u.w * w2a.w
              + v.x * w2b.x + v.y * w2b.y + v.z * w2b.z + v.w * w2b.w;
        a3[r] = u.x * w3a.x + u.y * w3a.y + u.z * w3a.z + u.w * w3a.w
              + v.x * w3b.x + v.y * w3b.y + v.z * w3b.z + v.w * w3b.w;
    }
    float s2 = reduce8(a2, lane);
    float s3 = reduce8(a3, lane);
    if ((lane & 3) == 0) {
        int R = 4 * ((lane >> 2) & 1) + 2 * ((lane >> 3) & 1) + ((lane >> 4) & 1);
        lhsS[(w << 3) + R] = w1 * s2;
        rhsS[(w << 3) + R] = s3;
    }
    __syncthreads();

    // ---- build tT[n][j] = tanh(lhs[j]*rhs[n] + bsT[n][j]) as bf16 hi/lo ----
    {
        const int n  = tid >> 2;
        const int j0 = (tid & 3) * 16;
        const float rv = rhsS[n];
        #pragma unroll
        for (int c = 0; c < 2; c++) {
            const int j = j0 + c * 8;
            float4 l0 = *(const float4*)(lhsS + j);
            float4 l1 = *(const float4*)(lhsS + j + 4);
            float4 b0 = *(const float4*)(g_bsT + n * 64 + j);
            float4 b1 = *(const float4*)(g_bsT + n * 64 + j + 4);
            float tv[8];
            tv[0] = fast_tanh(fmaf(l0.x, rv, b0.x));
            tv[1] = fast_tanh(fmaf(l0.y, rv, b0.y));
            tv[2] = fast_tanh(fmaf(l0.z, rv, b0.z));
            tv[3] = fast_tanh(fmaf(l0.w, rv, b0.w));
            tv[4] = fast_tanh(fmaf(l1.x, rv, b1.x));
            tv[5] = fast_tanh(fmaf(l1.y, rv, b1.y));
            tv[6] = fast_tanh(fmaf(l1.z, rv, b1.z));
            tv[7] = fast_tanh(fmaf(l1.w, rv, b1.w));
            uint4 hw, lw;
            float r0, r1;
            hw.x = pack_hi(tv[0], tv[1], r0, r1); lw.x = pack_lo(r0, r1);
            hw.y = pack_hi(tv[2], tv[3], r0, r1); lw.y = pack_lo(r0, r1);
            hw.z = pack_hi(tv[4], tv[5], r0, r1); lw.z = pack_lo(r0, r1);
            hw.w = pack_hi(tv[6], tv[7], r0, r1); lw.w = pack_lo(r0, r1);
            *(uint4*)((char*)tHiS + (n * PSTR + j) * 2) = hw;
            *(uint4*)((char*)tLoS + (n * PSTR + j) * 2) = lw;
        }
    }
    __syncthreads();

    // ---- warp-level GEMM: warp w -> rows 16*(w>>1).., cols 32*(w&1).. ----
    const int mt = w >> 1;
    const int nh = w & 1;

    const uint32_t sTHi = smem_u32(tHiS);
    const uint32_t sTLo = smem_u32(tLoS);

    const uint32_t bOff0 = (uint32_t)(((nh * 32 + (lane & 7) + ((lane >> 4) & 1) * 8) * PSTR
                                       + ((lane >> 3) & 1) * 8) * 2);
    const uint32_t bOff1 = bOff0 + (uint32_t)(16 * PSTR * 2);

    float acc[16];
    #pragma unroll
    for (int i = 0; i < 16; i++) acc[i] = 0.0f;

    const uint4* fHi = (const uint4*)g_AfHi;   // [(mt*4+ks)*32 + lane]
    const uint4* fLo = (const uint4*)g_AfLo;

    #pragma unroll
    for (int ks = 0; ks < 4; ks++) {
        const int fidx = (mt * 4 + ks) * 32 + lane;
        uint4 ah = fHi[fidx];
        uint4 al = fLo[fidx];
        const uint32_t joff = (uint32_t)(ks * 32);
        uint32_t bh0, bh1, bh2, bh3, bh4, bh5, bh6, bh7;
        uint32_t bl0, bl1, bl2, bl3, bl4, bl5, bl6, bl7;
        ldsm_x4(bh0, bh1, bh2, bh3, sTHi + bOff0 + joff);
        ldsm_x4(bh4, bh5, bh6, bh7, sTHi + bOff1 + joff);
        ldsm_x4(bl0, bl1, bl2, bl3, sTLo + bOff0 + joff);
        ldsm_x4(bl4, bl5, bl6, bl7, sTLo + bOff1 + joff);
        // Ah*Bh
        mma_bf16(acc[0],  acc[1],  acc[2],  acc[3],  ah.x, ah.y, ah.z, ah.w, bh0, bh1);
        mma_bf16(acc[4],  acc[5],  acc[6],  acc[7],  ah.x, ah.y, ah.z, ah.w, bh2, bh3);
        mma_bf16(acc[8],  acc[9],  acc[10], acc[11], ah.x, ah.y, ah.z, ah.w, bh4, bh5);
        mma_bf16(acc[12], acc[13], acc[14], acc[15], ah.x, ah.y, ah.z, ah.w, bh6, bh7);
        // Ah*Bl
        mma_bf16(acc[0],  acc[1],  acc[2],  acc[3],  ah.x, ah.y, ah.z, ah.w, bl0, bl1);
        mma_bf16(acc[4],  acc[5],  acc[6],  acc[7],  ah.x, ah.y, ah.z, ah.w, bl2, bl3);
        mma_bf16(acc[8],  acc[9],  acc[10], acc[11], ah.x, ah.y, ah.z, ah.w, bl4, bl5);
        mma_bf16(acc[12], acc[13], acc[14], acc[15], ah.x, ah.y, ah.z, ah.w, bl6, bl7);
        // Al*Bh
        mma_bf16(acc[0],  acc[1],  acc[2],  acc[3],  al.x, al.y, al.z, al.w, bh0, bh1);
        mma_bf16(acc[4],  acc[5],  acc[6],  acc[7],  al.x, al.y, al.z, al.w, bh2, bh3);
        mma_bf16(acc[8],  acc[9],  acc[10], acc[11], al.x, al.y, al.z, al.w, bh4, bh5);
        mma_bf16(acc[12], acc[13], acc[14], acc[15], al.x, al.y, al.z, al.w, bh6, bh7);
    }

    // ---- softmax over all 4096 scores of this batch element ----
    float m = acc[0];
    #pragma unroll
    for (int i = 1; i < 16; i++) m = fmaxf(m, acc[i]);
    #pragma unroll
    for (int sft = 16; sft > 0; sft >>= 1)
        m = fmaxf(m, __shfl_xor_sync(0xffffffffu, m, sft));
    if (lane == 0) redS[w] = m;
    __syncthreads();
    float bm = redS[0];
    #pragma unroll
    for (int i = 1; i < 8; i++) bm = fmaxf(bm, redS[i]);

    float lsum = 0.0f;
    #pragma unroll
    for (int i = 0; i < 16; i++) {
        acc[i] = __expf(acc[i] - bm);
        lsum += acc[i];
    }
    #pragma unroll
    for (int sft = 16; sft > 0; sft >>= 1)
        lsum += __shfl_xor_sync(0xffffffffu, lsum, sft);
    if (lane == 0) redS[8 + w] = lsum;
    __syncthreads();
    float tot = redS[8];
    #pragma unroll
    for (int i = 1; i < 8; i++) tot += redS[8 + i];
    const float inv = 1.0f / tot;

    // ---- store: rows {16mt+lane/4, +8}, cols 32nh + g*8 + (lane%4)*2 ----
    float* ob = out + (size_t)blockIdx.x * (NODES * NODES);
    const int row0 = 16 * mt + (lane >> 2);
    const int col0 = 32 * nh + (lane & 3) * 2;
    #pragma unroll
    for (int g = 0; g < 4; g++) {
        float2 o;
        o.x = acc[g * 4 + 0] * inv;
        o.y = acc[g * 4 + 1] * inv;
        *(float2*)(ob + row0 * NODES + col0 + g * 8) = o;
        o.x = acc[g * 4 + 2] * inv;
        o.y = acc[g * 4 + 3] * inv;
        *(float2*)(ob + (row0 + 8) * NODES + col0 + g * 8) = o;
    }
}

extern "C" void kernel_launch(void* const* d_in, const int* in_sizes, int n_in,
                              void* d_out, int out_size) {
    const float* x  = (const float*)d_in[0];
    const float* W1 = (const float*)d_in[1];
    const float* W2 = (const float*)d_in[2];
    const float* W3 = (const float*)d_in[3];
    const float* bs = (const float*)d_in[4];
    const float* Vs = (const float*)d_in[5];
    float* out = (float*)d_out;

    const int B = in_sizes[0] / (NODES * DIM);   // 4096
    precompute_kernel<<<16, 256>>>(bs, Vs);
    adj_attn_mma<<<B, TPB>>>(x, W1, W2, W3, out);
}